// round 3
// baseline (speedup 1.0000x reference)
#include <cuda_runtime.h>
#include <math.h>

#define kT   2048
#define kH   256
#define kE   64
#define kV   50257
#define kG   1024
#define kOW  50348   /* 2 + 64 + 25 + 50257 */

// ---------------- scratch (static device globals; no allocation) ----------------
__device__ float g_X [kT*kG];   // W_ih@emb[tok] + b_ih + b_hh
__device__ float g_H [kT*kH];   // h_t
__device__ float g_Gd[kT*kH];   // Wdelta @ h_t
__device__ float g_Ge[kT*kH];   // Went   @ h_t
__device__ float g_U [kT*kH];   // post-update entity vec at step t
__device__ float g_Ec[kT*kH];   // e_cur (pre-update) at step t
__device__ float g_Vv[kT*kH];   // h + We@e_cur + We_b
__device__ float g_Mr[2*kH];    // r_emb @ Wr_W
__device__ float g_W1[kH];      // row sums of Went
__device__ float g_lastt[kT*kE];
__device__ int   g_eidx [kT*kE];
__device__ int   g_slist[kE*kT];
__device__ int   g_scnt [kE];

// ---------------- helpers ----------------
__device__ __forceinline__ float sigf(float x){ return 1.0f/(1.0f+expf(-x)); }

__device__ __forceinline__ void fma2(unsigned long long &d, unsigned long long a, unsigned long long b){
  asm("fma.rn.f32x2 %0, %1, %2, %0;" : "+l"(d) : "l"(a), "l"(b));
}
__device__ __forceinline__ unsigned long long pk2(float lo, float hi){
  unsigned long long r; asm("mov.b64 %0, {%1,%2};" : "=l"(r) : "f"(lo), "f"(hi)); return r;
}
__device__ __forceinline__ void upk2(unsigned long long v, float &lo, float &hi){
  asm("mov.b64 {%0,%1}, %2;" : "=f"(lo), "=f"(hi) : "l"(v));
}
__device__ __forceinline__ unsigned smem_u32(const void* p){
  unsigned r;
  asm("{ .reg .u64 t; cvta.to.shared.u64 t, %1; cvt.u32.u64 %0, t; }" : "=r"(r) : "l"(p));
  return r;
}
__device__ __forceinline__ float wred(float v){
  #pragma unroll
  for (int o=16;o;o>>=1) v += __shfl_xor_sync(0xffffffffu, v, o);
  return v;
}

// ---------------- K1: tiny precomputes ----------------
__global__ void k_prep(const float* __restrict__ r_emb,
                       const float* __restrict__ WrW,
                       const float* __restrict__ WentW){
  const int k = threadIdx.x;   // 256 threads
  float m0=0.f, m1=0.f, w1=0.f;
  for (int j=0;j<kH;j++){
    float wr = WrW[j*kH+k];
    m0 += r_emb[j]    * wr;
    m1 += r_emb[kH+j] * wr;
    w1 += WentW[k*kH+j];
  }
  g_Mr[k]=m0; g_Mr[kH+k]=m1; g_W1[k]=w1;
}

// ---------------- K2: entity timing tables ----------------
__global__ void k_tables(const int* __restrict__ eids, const float* __restrict__ dist0){
  const int e = threadIdx.x;   // 64 threads
  float curt = dist0[e];
  int cidx = -1, cnt = 0;
  for (int t=0;t<kT;t++){
    g_lastt[t*kE+e] = curt;
    g_eidx [t*kE+e] = cidx;
    if (eids[t]==e){ curt=(float)t; cidx=t; g_slist[e*kT+cnt]=t; cnt++; }
  }
  g_scnt[e]=cnt;
}

// ---------------- K3: X = W_ih @ emb[tok] + b_ih + b_hh ----------------
__global__ void __launch_bounds__(128)
k_xgemm(const int* __restrict__ toks_g, const float* __restrict__ emb,
        const float* __restrict__ Wih, const float* __restrict__ bih,
        const float* __restrict__ bhh){
  __shared__ int   toks[32];
  __shared__ float As[32][33];
  __shared__ float Ws[128][33];
  const int tid = threadIdx.x;
  const int rb  = blockIdx.x*128;   // gate rows
  const int t0  = blockIdx.y*32;    // timesteps
  if (tid<32) toks[tid] = toks_g[t0+tid];
  __syncthreads();
  float acc[32];
  #pragma unroll
  for (int i=0;i<32;i++) acc[i]=0.f;
  for (int kc=0;kc<kH;kc+=32){
    for (int i=tid;i<1024;i+=128) As[i>>5][i&31] = emb[toks[i>>5]*kH + kc + (i&31)];
    for (int i=tid;i<4096;i+=128) Ws[i>>5][i&31] = Wih[(rb+(i>>5))*kH + kc + (i&31)];
    __syncthreads();
    #pragma unroll 8
    for (int kk=0;kk<32;kk++){
      float wv = Ws[tid][kk];
      #pragma unroll
      for (int ti=0;ti<32;ti++) acc[ti] += wv*As[ti][kk];
    }
    __syncthreads();
  }
  const int r = rb + tid;
  const float bb = bih[r] + bhh[r];
  #pragma unroll
  for (int ti=0;ti<32;ti++) g_X[(t0+ti)*kG + r] = acc[ti] + bb;
}

// ---------------- generic: out[t][r] = sum_k W[r][k]*A[t][k] (+bias[r]) (+add[t][r]) ----------------
__global__ void __launch_bounds__(128)
k_gemvT(const float* __restrict__ A, const float* __restrict__ W,
        float* __restrict__ out, const float* __restrict__ bias,
        const float* __restrict__ add){
  __shared__ float As[32][33];
  __shared__ float Ws[128][33];
  const int tid = threadIdx.x;
  const int rb  = blockIdx.x*128;
  const int t0  = blockIdx.y*32;
  float acc[32];
  #pragma unroll
  for (int i=0;i<32;i++) acc[i]=0.f;
  for (int kc=0;kc<kH;kc+=32){
    for (int i=tid;i<1024;i+=128) As[i>>5][i&31] = A[(t0+(i>>5))*kH + kc + (i&31)];
    for (int i=tid;i<4096;i+=128) Ws[i>>5][i&31] = W[(rb+(i>>5))*kH + kc + (i&31)];
    __syncthreads();
    #pragma unroll 8
    for (int kk=0;kk<32;kk++){
      float wv = Ws[tid][kk];
      #pragma unroll
      for (int ti=0;ti<32;ti++) acc[ti] += wv*As[ti][kk];
    }
    __syncthreads();
  }
  const int r = rb + tid;
  const float b = bias ? bias[r] : 0.f;
  #pragma unroll
  for (int ti=0;ti<32;ti++){
    float v = acc[ti] + b;
    if (add) v += add[(t0+ti)*kH + r];
    out[(t0+ti)*kH + r] = v;
  }
}

// ---------------- K4: sequential LSTM, 8-CTA cluster, W_hh in registers ----------------
__global__ void __cluster_dims__(8,1,1) __launch_bounds__(256,1)
k_lstm(const float* __restrict__ Whh){
  __shared__ float h_s[kH];
  __shared__ float part[256];
  __shared__ float gates[2][kG];
  const int tid  = threadIdx.x;
  const int half = tid >> 7;        // 0 or 1
  const int j    = tid & 127;
  unsigned rank; asm("mov.u32 %0, %%cluster_ctarank;" : "=r"(rank));
  const int rw = (int)rank*128 + j; // gate row this thread contributes to

  // load my 128 weights (as 64 packed float2)
  const unsigned long long* wp =
      (const unsigned long long*)(Whh + rw*kH + half*128);
  unsigned long long w[64];
  #pragma unroll
  for (int i=0;i<64;i++) w[i] = wp[i];

  h_s[tid] = 0.f;
  float c_r = 0.f;
  const unsigned gb0 = smem_u32(&gates[0][0]);
  __syncthreads();
  // cluster-wide: everyone ready before first DSMEM traffic
  asm volatile("barrier.cluster.arrive.aligned;" ::: "memory");
  asm volatile("barrier.cluster.wait.aligned;"   ::: "memory");

  int buf = 0;
  const ulonglong2* hbase = (const ulonglong2*)&h_s[half*128];

  for (int t=0; t<kT; t++){
    float xv = (tid<128) ? g_X[t*kG + (int)rank*128 + tid] : 0.f;

    unsigned long long acc_a = 0ull, acc_b = 0ull;
    #pragma unroll
    for (int q=0;q<32;q++){
      ulonglong2 hv = hbase[q];
      fma2(acc_a, w[2*q],   hv.x);
      fma2(acc_b, w[2*q+1], hv.y);
    }
    float a0,a1,b0,b1; upk2(acc_a,a0,a1); upk2(acc_b,b0,b1);
    part[tid] = (a0+a1)+(b0+b1);
    __syncthreads();

    if (tid < 128){
      float gate = part[tid] + part[tid+128] + xv;
      unsigned laddr = gb0 + (unsigned)buf*4096u + 4u*(unsigned)((int)rank*128 + tid);
      #pragma unroll
      for (int rk=0; rk<8; rk++){
        unsigned ra;
        asm("mapa.shared::cluster.u32 %0, %1, %2;" : "=r"(ra) : "r"(laddr), "r"(rk));
        asm volatile("st.shared::cluster.b32 [%0], %1;" :: "r"(ra), "f"(gate));
      }
    }
    asm volatile("barrier.cluster.arrive.aligned;" ::: "memory");
    asm volatile("barrier.cluster.wait.aligned;"   ::: "memory");

    // every CTA redundantly computes h,c from the full gate vector (local smem)
    float gi = gates[buf][tid];
    float gf = gates[buf][256+tid];
    float gg = gates[buf][512+tid];
    float go = gates[buf][768+tid];
    c_r = sigf(gf)*c_r + sigf(gi)*tanhf(gg);
    float hn = sigf(go)*tanhf(c_r);
    h_s[tid] = hn;
    if (rank==0) g_H[t*kH + tid] = hn;
    buf ^= 1;
    __syncthreads();
  }
}

// ---------------- K5: entity chains (one warp per entity) ----------------
__global__ void __launch_bounds__(32)
k_entity(const float* __restrict__ ents0, const float* __restrict__ Wdelta_b){
  const int e    = blockIdx.x;
  const int lane = threadIdx.x;
  const float db = Wdelta_b[0];
  float val[8];
  #pragma unroll
  for (int q=0;q<8;q++) val[q] = ents0[e*kH + q*32 + lane];

  const int n = g_scnt[e];
  for (int s=0;s<n;s++){
    const int t = g_slist[e*kT+s];
    float d1 = 0.f;
    #pragma unroll
    for (int q=0;q<8;q++){
      const int k = q*32+lane;
      g_Ec[t*kH+k] = val[q];
      d1 += val[q]*g_Gd[t*kH+k];
    }
    d1 = wred(d1);
    const float delta = sigf(d1 + db);
    float ss = 0.f;
    float u[8];
    #pragma unroll
    for (int q=0;q<8;q++){
      const int k = q*32+lane;
      u[q] = delta*val[q] + (1.f-delta)*g_H[t*kH+k];
      ss += u[q]*u[q];
    }
    ss = wred(ss);
    const float inv = 1.0f/sqrtf(ss);
    #pragma unroll
    for (int q=0;q<8;q++){
      val[q] = u[q]*inv;
      g_U[t*kH + q*32 + lane] = val[q];
    }
  }
}

// ---------------- K6: small heads (pred_r, pred_e, pred_l) ----------------
__global__ void __launch_bounds__(128)
k_heads(float* __restrict__ out,
        const float* __restrict__ Wr_b,   const float* __restrict__ WlenW,
        const float* __restrict__ Wlen_b, const float* __restrict__ Went_b,
        const float* __restrict__ wdW,    const float* __restrict__ wdb,
        const float* __restrict__ ents0){
  __shared__ float hs[kH], ges[kH], ecs[kH], w1s[kH];
  const int t    = blockIdx.x;
  const int tid  = threadIdx.x;
  const int warp = tid>>5, lane = tid&31;
  hs [tid]=g_H [t*kH+tid]; hs [tid+128]=g_H [t*kH+tid+128];
  ges[tid]=g_Ge[t*kH+tid]; ges[tid+128]=g_Ge[t*kH+tid+128];
  ecs[tid]=g_Ec[t*kH+tid]; ecs[tid+128]=g_Ec[t*kH+tid+128];
  w1s[tid]=g_W1[tid];      w1s[tid+128]=g_W1[tid+128];
  __syncthreads();
  float* orow = out + (size_t)t*kOW;

  // pred_r (warps 0,1)
  if (warp < 2){
    float s = 0.f;
    #pragma unroll
    for (int q=0;q<8;q++){ int k=q*32+lane; s += g_Mr[warp*kH+k]*hs[k]; }
    s = wred(s);
    if (lane==0) orow[warp] = s + Wr_b[0];
  }
  // pred_l (all warps, rows strided by 4)
  for (int r=warp; r<25; r+=4){
    float s = 0.f;
    #pragma unroll
    for (int q=0;q<16;q++){
      int k = q*32+lane;
      float xk = (k<kH) ? hs[k] : ecs[k-kH];
      s += WlenW[r*(2*kH)+k]*xk;
    }
    s = wred(s);
    if (lane==0) orow[66+r] = s + Wlen_b[r];
  }
  // pred_e (16 entities per warp)
  const float tf = (float)t;
  const float wdw = wdW[0], wdbv = wdb[0], geb = Went_b[0];
  for (int ei=0; ei<16; ei++){
    const int e = warp*16 + ei;
    const int ix = g_eidx[t*kE+e];
    const float* ep = (ix < 0) ? (ents0 + e*kH) : (g_U + (size_t)ix*kH);
    float s1=0.f, s2=0.f;
    #pragma unroll
    for (int q=0;q<8;q++){
      int k=q*32+lane;
      float ev = ep[k];
      s1 += ev*ges[k];
      s2 += ev*w1s[k];
    }
    s1 = wred(s1); s2 = wred(s2);
    if (lane==0){
      float dist = g_lastt[t*kE+e] - tf;
      float sc = dist*wdw + wdbv;
      orow[2+e] = s1 + sc*s2 + geb;
    }
  }
}

// ---------------- K7: logits GEMM  out[t][91+v] = Vv[t]·outW[v] + outb[v] ----------------
#define BM 128
#define BN 128
#define BK 32
__global__ void __launch_bounds__(256,2)
k_logits(const float* __restrict__ outW, const float* __restrict__ outb,
         float* __restrict__ out){
  __shared__ float As[BK][BM+4];
  __shared__ float Bs[BK][BN+4];
  const int tid = threadIdx.x;
  const int n0 = blockIdx.x*BN;
  const int m0 = blockIdx.y*BM;
  const int tx = tid&15, ty = tid>>4;

  unsigned long long acc[4][8];
  #pragma unroll
  for (int i=0;i<4;i++)
    #pragma unroll
    for (int jj=0;jj<8;jj++) acc[i][jj]=0ull;

  for (int kc=0; kc<kH; kc+=BK){
    #pragma unroll
    for (int l=0;l<4;l++){
      int idx = tid + 256*l;          // 0..1023
      int row = idx>>3;
      int kq  = idx&7;
      // A tile
      float4 av = *(const float4*)&g_Vv[(m0+row)*kH + kc + kq*4];
      As[kq*4+0][row]=av.x; As[kq*4+1][row]=av.y; As[kq*4+2][row]=av.z; As[kq*4+3][row]=av.w;
      // B tile (guard vocab edge)
      int v = n0 + row;
      float4 bv = make_float4(0.f,0.f,0.f,0.f);
      if (v < kV) bv = *(const float4*)&outW[v*kH + kc + kq*4];
      Bs[kq*4+0][row]=bv.x; Bs[kq*4+1][row]=bv.y; Bs[kq*4+2][row]=bv.z; Bs[kq*4+3][row]=bv.w;
    }
    __syncthreads();
    #pragma unroll
    for (int k=0;k<BK;k++){
      float4 a0 = *(const float4*)&As[k][ty*8];
      float4 a1 = *(const float4*)&As[k][ty*8+4];
      unsigned long long ap[4];
      ap[0]=pk2(a0.x,a0.y); ap[1]=pk2(a0.z,a0.w);
      ap[2]=pk2(a1.x,a1.y); ap[3]=pk2(a1.z,a1.w);
      float4 b0 = *(const float4*)&Bs[k][tx*8];
      float4 b1 = *(const float4*)&Bs[k][tx*8+4];
      unsigned long long bb[8];
      bb[0]=pk2(b0.x,b0.x); bb[1]=pk2(b0.y,b0.y); bb[2]=pk2(b0.z,b0.z); bb[3]=pk2(b0.w,b0.w);
      bb[4]=pk2(b1.x,b1.x); bb[5]=pk2(b1.y,b1.y); bb[6]=pk2(b1.z,b1.z); bb[7]=pk2(b1.w,b1.w);
      #pragma unroll
      for (int ip=0; ip<4; ip++)
        #pragma unroll
        for (int jj=0; jj<8; jj++)
          fma2(acc[ip][jj], ap[ip], bb[jj]);
    }
    __syncthreads();
  }

  const int c0 = n0 + tx*8;
  float bvals[8];
  #pragma unroll
  for (int jj=0;jj<8;jj++) bvals[jj] = (c0+jj < kV) ? outb[c0+jj] : 0.f;
  #pragma unroll
  for (int ip=0; ip<4; ip++){
    const int r0 = m0 + ty*8 + 2*ip;
    float* o0 = out + (size_t)r0*kOW + 91 + c0;
    float* o1 = o0 + kOW;
    #pragma unroll
    for (int jj=0;jj<8;jj++){
      if (c0+jj < kV){
        float lo,hi; upk2(acc[ip][jj], lo, hi);
        o0[jj] = lo + bvals[jj];
        o1[jj] = hi + bvals[jj];
      }
    }
  }
}

// ---------------- launch ----------------
extern "C" void kernel_launch(void* const* d_in, const int* in_sizes, int n_in,
                              void* d_out, int out_size){
  const int*   tokens  = (const int*)  d_in[0];
  const int*   eids    = (const int*)  d_in[1];
  const float* emb     = (const float*)d_in[2];
  const float* W_ih    = (const float*)d_in[3];
  const float* W_hh    = (const float*)d_in[4];
  const float* b_ih    = (const float*)d_in[5];
  const float* b_hh    = (const float*)d_in[6];
  const float* out_W   = (const float*)d_in[7];
  const float* out_b   = (const float*)d_in[8];
  const float* r_emb   = (const float*)d_in[9];
  const float* Wr_W    = (const float*)d_in[10];
  const float* Wr_b    = (const float*)d_in[11];
  const float* Wlen_W  = (const float*)d_in[12];
  const float* Wlen_b  = (const float*)d_in[13];
  const float* Went_W  = (const float*)d_in[14];
  const float* Went_b  = (const float*)d_in[15];
  const float* wdist_W = (const float*)d_in[16];
  const float* wdist_b = (const float*)d_in[17];
  const float* Wdelta_W= (const float*)d_in[18];
  const float* Wdelta_b= (const float*)d_in[19];
  const float* We_W    = (const float*)d_in[20];
  const float* We_b    = (const float*)d_in[21];
  const float* ents0   = (const float*)d_in[22];
  const float* dist0   = (const float*)d_in[23];
  float* out = (float*)d_out;

  float *gX, *gH, *gGd, *gGe, *gU, *gEc, *gVv;
  cudaGetSymbolAddress((void**)&gX,  g_X);
  cudaGetSymbolAddress((void**)&gH,  g_H);
  cudaGetSymbolAddress((void**)&gGd, g_Gd);
  cudaGetSymbolAddress((void**)&gGe, g_Ge);
  cudaGetSymbolAddress((void**)&gU,  g_U);
  cudaGetSymbolAddress((void**)&gEc, g_Ec);
  cudaGetSymbolAddress((void**)&gVv, g_Vv);

  k_prep  <<<1, 256>>>(r_emb, Wr_W, Went_W);
  k_tables<<<1, 64>>>(eids, dist0);
  k_xgemm <<<dim3(8,64), 128>>>(tokens, emb, W_ih, b_ih, b_hh);
  k_lstm  <<<8, 256>>>(W_hh);
  k_gemvT <<<dim3(2,64), 128>>>(gH,  Wdelta_W, gGd, (const float*)0, (const float*)0);
  k_gemvT <<<dim3(2,64), 128>>>(gH,  Went_W,   gGe, (const float*)0, (const float*)0);
  k_entity<<<64, 32>>>(ents0, Wdelta_b);
  k_gemvT <<<dim3(2,64), 128>>>(gEc, We_W,     gVv, We_b, gH);
  k_heads <<<kT, 128>>>(out, Wr_b, Wlen_W, Wlen_b, Went_b, wdist_W, wdist_b, ents0);
  k_logits<<<dim3((kV+BN-1)/BN, kT/BM), 256>>>(out_W, out_b, out);
}

// round 4
// speedup vs baseline: 1.2430x; 1.2430x over previous
#include <cuda_runtime.h>
#include <math.h>

#define kT   2048
#define kH   256
#define kE   64
#define kV   50257
#define kG   1024
#define kOW  50348   /* 2 + 64 + 25 + 50257 */

// ---------------- scratch (static device globals; no allocation) ----------------
__device__ float g_X [kT*kG];   // W_ih@emb[tok] + b_ih + b_hh
__device__ float g_H [kT*kH];   // h_t
__device__ float g_Gd[kT*kH];   // Wdelta @ h_t
__device__ float g_Ge[kT*kH];   // Went   @ h_t
__device__ float g_U [kT*kH];   // post-update entity vec at step t
__device__ float g_Ec[kT*kH];   // e_cur (pre-update) at step t
__device__ float g_Vv[kT*kH];   // h + We@e_cur + We_b
__device__ float g_Mr[2*kH];    // r_emb @ Wr_W
__device__ float g_W1[kH];      // row sums of Went
__device__ float g_lastt[kT*kE];
__device__ int   g_eidx [kT*kE];
__device__ int   g_slist[kE*kT];
__device__ int   g_scnt [kE];

// ---------------- helpers ----------------
__device__ __forceinline__ float sigf(float x){ return 1.0f/(1.0f+expf(-x)); }
__device__ __forceinline__ float fsig(float x){ return __fdividef(1.0f, 1.0f + __expf(-x)); }
__device__ __forceinline__ float ftanh(float x){ return __fdividef(2.0f, 1.0f + __expf(-2.0f*x)) - 1.0f; }

__device__ __forceinline__ void fma2(unsigned long long &d, unsigned long long a, unsigned long long b){
  asm("fma.rn.f32x2 %0, %1, %2, %0;" : "+l"(d) : "l"(a), "l"(b));
}
__device__ __forceinline__ unsigned long long pk2(float lo, float hi){
  unsigned long long r; asm("mov.b64 %0, {%1,%2};" : "=l"(r) : "f"(lo), "f"(hi)); return r;
}
__device__ __forceinline__ void upk2(unsigned long long v, float &lo, float &hi){
  asm("mov.b64 {%0,%1}, %2;" : "=f"(lo), "=f"(hi) : "l"(v));
}
__device__ __forceinline__ unsigned smem_u32(const void* p){
  unsigned r;
  asm("{ .reg .u64 t; cvta.to.shared.u64 t, %1; cvt.u32.u64 %0, t; }" : "=r"(r) : "l"(p));
  return r;
}
__device__ __forceinline__ float wred(float v){
  #pragma unroll
  for (int o=16;o;o>>=1) v += __shfl_xor_sync(0xffffffffu, v, o);
  return v;
}
__device__ __forceinline__ void mbar_init(unsigned a, unsigned cnt){
  asm volatile("mbarrier.init.shared.b64 [%0], %1;" :: "r"(a), "r"(cnt) : "memory");
}
__device__ __forceinline__ void mbar_expect(unsigned a, unsigned tx){
  asm volatile("mbarrier.arrive.expect_tx.shared.b64 _, [%0], %1;" :: "r"(a), "r"(tx) : "memory");
}
__device__ __forceinline__ void mbar_waitp(unsigned a, unsigned ph){
  unsigned done;
  asm volatile("{\n\t.reg .pred p;\n\t"
               "mbarrier.try_wait.parity.acquire.cta.shared::cta.b64 p, [%1], %2;\n\t"
               "selp.b32 %0, 1, 0, p;\n\t}"
               : "=r"(done) : "r"(a), "r"(ph) : "memory");
  if (!done){
    asm volatile("{\n\t.reg .pred P1;\n\t"
                 "WL_%=:\n\t"
                 "mbarrier.try_wait.parity.acquire.cta.shared::cta.b64 P1, [%0], %1, 0x989680;\n\t"
                 "@P1 bra.uni WD_%=;\n\t"
                 "bra.uni WL_%=;\n\t"
                 "WD_%=:\n\t}"
                 :: "r"(a), "r"(ph) : "memory");
  }
}
__device__ __forceinline__ void st_async_remote(unsigned dst, float v, unsigned mb){
  asm volatile("st.async.shared::cluster.mbarrier::complete_tx::bytes.u32 [%0], %1, [%2];"
               :: "r"(dst), "r"(__float_as_uint(v)), "r"(mb) : "memory");
}

// ---------------- K1: tiny precomputes ----------------
__global__ void k_prep(const float* __restrict__ r_emb,
                       const float* __restrict__ WrW,
                       const float* __restrict__ WentW){
  const int k = threadIdx.x;   // 256 threads
  float m0=0.f, m1=0.f, w1=0.f;
  for (int j=0;j<kH;j++){
    float wr = WrW[j*kH+k];
    m0 += r_emb[j]    * wr;
    m1 += r_emb[kH+j] * wr;
    w1 += WentW[k*kH+j];
  }
  g_Mr[k]=m0; g_Mr[kH+k]=m1; g_W1[k]=w1;
}

// ---------------- K2: entity timing tables ----------------
__global__ void k_tables(const int* __restrict__ eids, const float* __restrict__ dist0){
  const int e = threadIdx.x;   // 64 threads
  float curt = dist0[e];
  int cidx = -1, cnt = 0;
  for (int t=0;t<kT;t++){
    g_lastt[t*kE+e] = curt;
    g_eidx [t*kE+e] = cidx;
    if (eids[t]==e){ curt=(float)t; cidx=t; g_slist[e*kT+cnt]=t; cnt++; }
  }
  g_scnt[e]=cnt;
}

// ---------------- K3: X = W_ih @ emb[tok] + b_ih + b_hh ----------------
__global__ void __launch_bounds__(128)
k_xgemm(const int* __restrict__ toks_g, const float* __restrict__ emb,
        const float* __restrict__ Wih, const float* __restrict__ bih,
        const float* __restrict__ bhh){
  __shared__ int   toks[32];
  __shared__ float As[32][33];
  __shared__ float Ws[128][33];
  const int tid = threadIdx.x;
  const int rb  = blockIdx.x*128;   // gate rows
  const int t0  = blockIdx.y*32;    // timesteps
  if (tid<32) toks[tid] = toks_g[t0+tid];
  __syncthreads();
  float acc[32];
  #pragma unroll
  for (int i=0;i<32;i++) acc[i]=0.f;
  for (int kc=0;kc<kH;kc+=32){
    for (int i=tid;i<1024;i+=128) As[i>>5][i&31] = emb[toks[i>>5]*kH + kc + (i&31)];
    for (int i=tid;i<4096;i+=128) Ws[i>>5][i&31] = Wih[(rb+(i>>5))*kH + kc + (i&31)];
    __syncthreads();
    #pragma unroll 8
    for (int kk=0;kk<32;kk++){
      float wv = Ws[tid][kk];
      #pragma unroll
      for (int ti=0;ti<32;ti++) acc[ti] += wv*As[ti][kk];
    }
    __syncthreads();
  }
  const int r = rb + tid;
  const float bb = bih[r] + bhh[r];
  #pragma unroll
  for (int ti=0;ti<32;ti++) g_X[(t0+ti)*kG + r] = acc[ti] + bb;
}

// ---------------- generic: out[t][r] = sum_k W[r][k]*A[t][k] (+bias[r]) (+add[t][r]) ----------------
__global__ void __launch_bounds__(128)
k_gemvT(const float* __restrict__ A, const float* __restrict__ W,
        float* __restrict__ out, const float* __restrict__ bias,
        const float* __restrict__ add){
  __shared__ float As[32][33];
  __shared__ float Ws[128][33];
  const int tid = threadIdx.x;
  const int rb  = blockIdx.x*128;
  const int t0  = blockIdx.y*32;
  float acc[32];
  #pragma unroll
  for (int i=0;i<32;i++) acc[i]=0.f;
  for (int kc=0;kc<kH;kc+=32){
    for (int i=tid;i<1024;i+=128) As[i>>5][i&31] = A[(t0+(i>>5))*kH + kc + (i&31)];
    for (int i=tid;i<4096;i+=128) Ws[i>>5][i&31] = W[(rb+(i>>5))*kH + kc + (i&31)];
    __syncthreads();
    #pragma unroll 8
    for (int kk=0;kk<32;kk++){
      float wv = Ws[tid][kk];
      #pragma unroll
      for (int ti=0;ti<32;ti++) acc[ti] += wv*As[ti][kk];
    }
    __syncthreads();
  }
  const int r = rb + tid;
  const float b = bias ? bias[r] : 0.f;
  #pragma unroll
  for (int ti=0;ti<32;ti++){
    float v = acc[ti] + b;
    if (add) v += add[(t0+ti)*kH + r];
    out[(t0+ti)*kH + r] = v;
  }
}

// ---------------- K4: sequential LSTM, 8-CTA cluster ----------------
// CTA c owns all 4 gate rows for h-slice [32c, 32c+32): row_g = gate*256 + c*32 + idx.
// h computed locally by 1 warp, broadcast (32 floats) to all CTAs via st.async +
// tx-counted mbarrier (no barrier.cluster in the loop).
__global__ void __cluster_dims__(8,1,1) __launch_bounds__(256,1)
k_lstm(const float* __restrict__ Whh){
  __shared__ float h_s[2][kH];                 // double-buffered h
  __shared__ float part[256];
  __shared__ float gv[128];
  __shared__ __align__(8) unsigned long long mbar[2];
  const int tid  = threadIdx.x;
  const int half = tid >> 7;
  const int j    = tid & 127;
  const int gate = j >> 5;
  const int idx  = j & 31;
  unsigned rank; asm("mov.u32 %0, %%cluster_ctarank;" : "=r"(rank));
  const int c = (int)rank;
  const int row_g = gate*256 + c*32 + idx;

  // my 128 weights as 64 packed float2
  const unsigned long long* wp = (const unsigned long long*)(Whh + row_g*kH + half*128);
  unsigned long long w[64];
  #pragma unroll
  for (int i=0;i<64;i++) w[i] = wp[i];

  h_s[0][tid] = 0.f;
  h_s[1][tid] = 0.f;                           // step 0 reads buffer 1 (h(-1)=0)
  if (tid==0){
    mbar_init(smem_u32(&mbar[0]), 1);
    mbar_init(smem_u32(&mbar[1]), 1);
  }
  __syncthreads();
  asm volatile("barrier.cluster.arrive.aligned;" ::: "memory");
  asm volatile("barrier.cluster.wait.aligned;"   ::: "memory");

  // remote addresses for my h element (meaningful for tid<32)
  const int kk = c*32 + (tid & 31);
  unsigned rh[8], rmb[8];
  {
    unsigned lh = smem_u32(&h_s[0][kk]);
    unsigned lm = smem_u32(&mbar[0]);
    #pragma unroll
    for (int rk=0; rk<8; rk++){
      asm("mapa.shared::cluster.u32 %0, %1, %2;" : "=r"(rh[rk])  : "r"(lh), "r"(rk));
      asm("mapa.shared::cluster.u32 %0, %1, %2;" : "=r"(rmb[rk]) : "r"(lm), "r"(rk));
    }
  }
  const unsigned lmbar0 = smem_u32(&mbar[0]);

  float c_r = 0.f;                             // cell state for element kk (tid<32)
  float xv  = (tid<128) ? g_X[row_g] : 0.f;    // prefetch t=0
  int ph0 = 0, ph1 = 0;

  for (int t=0; t<kT; t++){
    const int buf  = t & 1;                    // h(t) buffer
    const int pbuf = buf ^ 1;                  // h(t-1) buffer

    // matvec: part = w . h_prev (broadcast LDS)
    const ulonglong2* hb = (const ulonglong2*)&h_s[pbuf][half*128];
    unsigned long long acc_a = 0ull, acc_b = 0ull;
    #pragma unroll
    for (int q=0;q<32;q++){
      ulonglong2 hv = hb[q];
      fma2(acc_a, w[2*q],   hv.x);
      fma2(acc_b, w[2*q+1], hv.y);
    }
    float a0,a1,b0,b1; upk2(acc_a,a0,a1); upk2(acc_b,b0,b1);
    part[tid] = (a0+a1)+(b0+b1);
    __syncthreads();                            // sync A

    if (tid < 128) gv[tid] = part[tid] + part[tid+128] + xv;
    if (tid < 128 && t+1 < kT) xv = g_X[(t+1)*kG + row_g];   // prefetch next x
    if (tid == 128) mbar_expect(lmbar0 + (unsigned)buf*8u, 1024u);
    __syncthreads();                            // sync B

    if (tid < 32){
      float gi = gv[tid], gf = gv[32+tid], gg = gv[64+tid], go = gv[96+tid];
      c_r = fsig(gf)*c_r + fsig(gi)*ftanh(gg);
      float hn = fsig(go)*ftanh(c_r);
      g_H[t*kH + kk] = hn;
      #pragma unroll
      for (int rk=0; rk<8; rk++)
        st_async_remote(rh[rk] + (unsigned)buf*1024u, hn, rmb[rk] + (unsigned)buf*8u);
    }

    // wait for all 8 CTAs' h slices (1024 bytes) to land in h_s[buf]
    if (buf==0){ mbar_waitp(lmbar0, (unsigned)ph0); ph0 ^= 1; }
    else       { mbar_waitp(lmbar0 + 8u, (unsigned)ph1); ph1 ^= 1; }
  }

  asm volatile("barrier.cluster.arrive.aligned;" ::: "memory");
  asm volatile("barrier.cluster.wait.aligned;"   ::: "memory");
}

// ---------------- K5: entity chains (one warp per entity) ----------------
__global__ void __launch_bounds__(32)
k_entity(const float* __restrict__ ents0, const float* __restrict__ Wdelta_b){
  const int e    = blockIdx.x;
  const int lane = threadIdx.x;
  const float db = Wdelta_b[0];
  float val[8];
  #pragma unroll
  for (int q=0;q<8;q++) val[q] = ents0[e*kH + q*32 + lane];

  const int n = g_scnt[e];
  for (int s=0;s<n;s++){
    const int t = g_slist[e*kT+s];
    float d1 = 0.f;
    #pragma unroll
    for (int q=0;q<8;q++){
      const int k = q*32+lane;
      g_Ec[t*kH+k] = val[q];
      d1 += val[q]*g_Gd[t*kH+k];
    }
    d1 = wred(d1);
    const float delta = sigf(d1 + db);
    float ss = 0.f;
    float u[8];
    #pragma unroll
    for (int q=0;q<8;q++){
      const int k = q*32+lane;
      u[q] = delta*val[q] + (1.f-delta)*g_H[t*kH+k];
      ss += u[q]*u[q];
    }
    ss = wred(ss);
    const float inv = 1.0f/sqrtf(ss);
    #pragma unroll
    for (int q=0;q<8;q++){
      val[q] = u[q]*inv;
      g_U[t*kH + q*32 + lane] = val[q];
    }
  }
}

// ---------------- K6: small heads (pred_r, pred_e, pred_l) ----------------
__global__ void __launch_bounds__(128)
k_heads(float* __restrict__ out,
        const float* __restrict__ Wr_b,   const float* __restrict__ WlenW,
        const float* __restrict__ Wlen_b, const float* __restrict__ Went_b,
        const float* __restrict__ wdW,    const float* __restrict__ wdb,
        const float* __restrict__ ents0){
  __shared__ float hs[kH], ges[kH], ecs[kH], w1s[kH];
  const int t    = blockIdx.x;
  const int tid  = threadIdx.x;
  const int warp = tid>>5, lane = tid&31;
  hs [tid]=g_H [t*kH+tid]; hs [tid+128]=g_H [t*kH+tid+128];
  ges[tid]=g_Ge[t*kH+tid]; ges[tid+128]=g_Ge[t*kH+tid+128];
  ecs[tid]=g_Ec[t*kH+tid]; ecs[tid+128]=g_Ec[t*kH+tid+128];
  w1s[tid]=g_W1[tid];      w1s[tid+128]=g_W1[tid+128];
  __syncthreads();
  float* orow = out + (size_t)t*kOW;

  // pred_r (warps 0,1)
  if (warp < 2){
    float s = 0.f;
    #pragma unroll
    for (int q=0;q<8;q++){ int k=q*32+lane; s += g_Mr[warp*kH+k]*hs[k]; }
    s = wred(s);
    if (lane==0) orow[warp] = s + Wr_b[0];
  }
  // pred_l (all warps, rows strided by 4)
  for (int r=warp; r<25; r+=4){
    float s = 0.f;
    #pragma unroll
    for (int q=0;q<16;q++){
      int k = q*32+lane;
      float xk = (k<kH) ? hs[k] : ecs[k-kH];
      s += WlenW[r*(2*kH)+k]*xk;
    }
    s = wred(s);
    if (lane==0) orow[66+r] = s + Wlen_b[r];
  }
  // pred_e (16 entities per warp)
  const float tf = (float)t;
  const float wdw = wdW[0], wdbv = wdb[0], geb = Went_b[0];
  for (int ei=0; ei<16; ei++){
    const int e = warp*16 + ei;
    const int ix = g_eidx[t*kE+e];
    const float* ep = (ix < 0) ? (ents0 + e*kH) : (g_U + (size_t)ix*kH);
    float s1=0.f, s2=0.f;
    #pragma unroll
    for (int q=0;q<8;q++){
      int k=q*32+lane;
      float ev = ep[k];
      s1 += ev*ges[k];
      s2 += ev*w1s[k];
    }
    s1 = wred(s1); s2 = wred(s2);
    if (lane==0){
      float dist = g_lastt[t*kE+e] - tf;
      float sc = dist*wdw + wdbv;
      orow[2+e] = s1 + sc*s2 + geb;
    }
  }
}

// ---------------- K7: logits GEMM  out[t][91+v] = Vv[t]·outW[v] + outb[v] ----------------
#define BM 128
#define BN 128
#define BK 32
__global__ void __launch_bounds__(256,2)
k_logits(const float* __restrict__ outW, const float* __restrict__ outb,
         float* __restrict__ out){
  __shared__ float As[BK][BM+4];
  __shared__ float Bs[BK][BN+4];
  const int tid = threadIdx.x;
  const int n0 = blockIdx.x*BN;
  const int m0 = blockIdx.y*BM;
  const int tx = tid&15, ty = tid>>4;

  unsigned long long acc[4][8];
  #pragma unroll
  for (int i=0;i<4;i++)
    #pragma unroll
    for (int jj=0;jj<8;jj++) acc[i][jj]=0ull;

  for (int kc=0; kc<kH; kc+=BK){
    #pragma unroll
    for (int l=0;l<4;l++){
      int idx = tid + 256*l;          // 0..1023
      int row = idx>>3;
      int kq  = idx&7;
      // A tile
      float4 av = *(const float4*)&g_Vv[(m0+row)*kH + kc + kq*4];
      As[kq*4+0][row]=av.x; As[kq*4+1][row]=av.y; As[kq*4+2][row]=av.z; As[kq*4+3][row]=av.w;
      // B tile (guard vocab edge)
      int v = n0 + row;
      float4 bv = make_float4(0.f,0.f,0.f,0.f);
      if (v < kV) bv = *(const float4*)&outW[v*kH + kc + kq*4];
      Bs[kq*4+0][row]=bv.x; Bs[kq*4+1][row]=bv.y; Bs[kq*4+2][row]=bv.z; Bs[kq*4+3][row]=bv.w;
    }
    __syncthreads();
    #pragma unroll
    for (int k=0;k<BK;k++){
      float4 a0 = *(const float4*)&As[k][ty*8];
      float4 a1 = *(const float4*)&As[k][ty*8+4];
      unsigned long long ap[4];
      ap[0]=pk2(a0.x,a0.y); ap[1]=pk2(a0.z,a0.w);
      ap[2]=pk2(a1.x,a1.y); ap[3]=pk2(a1.z,a1.w);
      float4 b0 = *(const float4*)&Bs[k][tx*8];
      float4 b1 = *(const float4*)&Bs[k][tx*8+4];
      unsigned long long bb[8];
      bb[0]=pk2(b0.x,b0.x); bb[1]=pk2(b0.y,b0.y); bb[2]=pk2(b0.z,b0.z); bb[3]=pk2(b0.w,b0.w);
      bb[4]=pk2(b1.x,b1.x); bb[5]=pk2(b1.y,b1.y); bb[6]=pk2(b1.z,b1.z); bb[7]=pk2(b1.w,b1.w);
      #pragma unroll
      for (int ip=0; ip<4; ip++)
        #pragma unroll
        for (int jj=0; jj<8; jj++)
          fma2(acc[ip][jj], ap[ip], bb[jj]);
    }
    __syncthreads();
  }

  const int c0 = n0 + tx*8;
  float bvals[8];
  #pragma unroll
  for (int jj=0;jj<8;jj++) bvals[jj] = (c0+jj < kV) ? outb[c0+jj] : 0.f;
  #pragma unroll
  for (int ip=0; ip<4; ip++){
    const int r0 = m0 + ty*8 + 2*ip;
    float* o0 = out + (size_t)r0*kOW + 91 + c0;
    float* o1 = o0 + kOW;
    #pragma unroll
    for (int jj=0;jj<8;jj++){
      if (c0+jj < kV){
        float lo,hi; upk2(acc[ip][jj], lo, hi);
        o0[jj] = lo + bvals[jj];
        o1[jj] = hi + bvals[jj];
      }
    }
  }
}

// ---------------- launch ----------------
extern "C" void kernel_launch(void* const* d_in, const int* in_sizes, int n_in,
                              void* d_out, int out_size){
  const int*   tokens  = (const int*)  d_in[0];
  const int*   eids    = (const int*)  d_in[1];
  const float* emb     = (const float*)d_in[2];
  const float* W_ih    = (const float*)d_in[3];
  const float* W_hh    = (const float*)d_in[4];
  const float* b_ih    = (const float*)d_in[5];
  const float* b_hh    = (const float*)d_in[6];
  const float* out_W   = (const float*)d_in[7];
  const float* out_b   = (const float*)d_in[8];
  const float* r_emb   = (const float*)d_in[9];
  const float* Wr_W    = (const float*)d_in[10];
  const float* Wr_b    = (const float*)d_in[11];
  const float* Wlen_W  = (const float*)d_in[12];
  const float* Wlen_b  = (const float*)d_in[13];
  const float* Went_W  = (const float*)d_in[14];
  const float* Went_b  = (const float*)d_in[15];
  const float* wdist_W = (const float*)d_in[16];
  const float* wdist_b = (const float*)d_in[17];
  const float* Wdelta_W= (const float*)d_in[18];
  const float* Wdelta_b= (const float*)d_in[19];
  const float* We_W    = (const float*)d_in[20];
  const float* We_b    = (const float*)d_in[21];
  const float* ents0   = (const float*)d_in[22];
  const float* dist0   = (const float*)d_in[23];
  float* out = (float*)d_out;

  float *gX, *gH, *gGd, *gGe, *gU, *gEc, *gVv;
  cudaGetSymbolAddress((void**)&gX,  g_X);
  cudaGetSymbolAddress((void**)&gH,  g_H);
  cudaGetSymbolAddress((void**)&gGd, g_Gd);
  cudaGetSymbolAddress((void**)&gGe, g_Ge);
  cudaGetSymbolAddress((void**)&gU,  g_U);
  cudaGetSymbolAddress((void**)&gEc, g_Ec);
  cudaGetSymbolAddress((void**)&gVv, g_Vv);

  k_prep  <<<1, 256>>>(r_emb, Wr_W, Went_W);
  k_tables<<<1, 64>>>(eids, dist0);
  k_xgemm <<<dim3(8,64), 128>>>(tokens, emb, W_ih, b_ih, b_hh);
  k_lstm  <<<8, 256>>>(W_hh);
  k_gemvT <<<dim3(2,64), 128>>>(gH,  Wdelta_W, gGd, (const float*)0, (const float*)0);
  k_gemvT <<<dim3(2,64), 128>>>(gH,  Went_W,   gGe, (const float*)0, (const float*)0);
  k_entity<<<64, 32>>>(ents0, Wdelta_b);
  k_gemvT <<<dim3(2,64), 128>>>(gEc, We_W,     gVv, We_b, gH);
  k_heads <<<kT, 128>>>(out, Wr_b, Wlen_W, Wlen_b, Went_b, wdist_W, wdist_b, ents0);
  k_logits<<<dim3((kV+BN-1)/BN, kT/BM), 256>>>(out_W, out_b, out);
}

// round 7
// speedup vs baseline: 1.2981x; 1.0443x over previous
#include <cuda_runtime.h>
#include <math.h>

#define kT   2048
#define kH   256
#define kE   64
#define kV   50257
#define kG   1024
#define kOW  50348   /* 2 + 64 + 25 + 50257 */

// ---------------- scratch (static device globals; no allocation) ----------------
__device__ float g_X [kT*kG];   // W_ih@emb[tok] + b_ih + b_hh
__device__ float g_H [kT*kH];   // h_t
__device__ float g_Gd[kT*kH];   // Wdelta @ h_t
__device__ float g_Ge[kT*kH];   // Went   @ h_t
__device__ float g_U [kT*kH];   // post-update entity vec at step t
__device__ float g_Ec[kT*kH];   // e_cur (pre-update) at step t
__device__ float g_Vv[kT*kH];   // h + We@e_cur + We_b
__device__ float g_Mr[2*kH];    // r_emb @ Wr_W
__device__ float g_W1[kH];      // row sums of Went
__device__ float g_lastt[kT*kE];
__device__ int   g_eidx [kT*kE];
__device__ int   g_slist[kE*kT];
__device__ int   g_scnt [kE];

// ---------------- helpers ----------------
__device__ __forceinline__ float sigf(float x){ return 1.0f/(1.0f+expf(-x)); }
__device__ __forceinline__ float fsig(float x){ return __fdividef(1.0f, 1.0f + __expf(-x)); }
__device__ __forceinline__ float ftanh(float x){ return __fdividef(2.0f, 1.0f + __expf(-2.0f*x)) - 1.0f; }

__device__ __forceinline__ void fma2(unsigned long long &d, unsigned long long a, unsigned long long b){
  asm("fma.rn.f32x2 %0, %1, %2, %0;" : "+l"(d) : "l"(a), "l"(b));
}
__device__ __forceinline__ unsigned long long pk2(float lo, float hi){
  unsigned long long r; asm("mov.b64 %0, {%1,%2};" : "=l"(r) : "f"(lo), "f"(hi)); return r;
}
__device__ __forceinline__ void upk2(unsigned long long v, float &lo, float &hi){
  asm("mov.b64 {%0,%1}, %2;" : "=f"(lo), "=f"(hi) : "l"(v));
}
__device__ __forceinline__ unsigned smem_u32(const void* p){
  unsigned r;
  asm("{ .reg .u64 t; cvta.to.shared.u64 t, %1; cvt.u32.u64 %0, t; }" : "=r"(r) : "l"(p));
  return r;
}
__device__ __forceinline__ float wred(float v){
  #pragma unroll
  for (int o=16;o;o>>=1) v += __shfl_xor_sync(0xffffffffu, v, o);
  return v;
}
__device__ __forceinline__ void mbar_init(unsigned a, unsigned cnt){
  asm volatile("mbarrier.init.shared.b64 [%0], %1;" :: "r"(a), "r"(cnt) : "memory");
}
__device__ __forceinline__ void mbar_expect(unsigned a, unsigned tx){
  asm volatile("mbarrier.arrive.expect_tx.shared.b64 _, [%0], %1;" :: "r"(a), "r"(tx) : "memory");
}
__device__ __forceinline__ void mbar_waitp(unsigned a, unsigned ph){
  unsigned done;
  asm volatile("{\n\t.reg .pred p;\n\t"
               "mbarrier.try_wait.parity.acquire.cluster.shared::cta.b64 p, [%1], %2;\n\t"
               "selp.b32 %0, 1, 0, p;\n\t}"
               : "=r"(done) : "r"(a), "r"(ph) : "memory");
  if (!done){
    asm volatile("{\n\t.reg .pred P1;\n\t"
                 "WL_%=:\n\t"
                 "mbarrier.try_wait.parity.acquire.cluster.shared::cta.b64 P1, [%0], %1, 0x989680;\n\t"
                 "@P1 bra.uni WD_%=;\n\t"
                 "bra.uni WL_%=;\n\t"
                 "WD_%=:\n\t}"
                 :: "r"(a), "r"(ph) : "memory");
  }
}
__device__ __forceinline__ void st_async_remote(unsigned dst, float v, unsigned mb){
  asm volatile("st.async.shared::cluster.mbarrier::complete_tx::bytes.u32 [%0], %1, [%2];"
               :: "r"(dst), "r"(__float_as_uint(v)), "r"(mb) : "memory");
}

// ---------------- K1: tiny precomputes ----------------
__global__ void k_prep(const float* __restrict__ r_emb,
                       const float* __restrict__ WrW,
                       const float* __restrict__ WentW){
  const int k = threadIdx.x;   // 256 threads
  float m0=0.f, m1=0.f, w1=0.f;
  for (int j=0;j<kH;j++){
    float wr = WrW[j*kH+k];
    m0 += r_emb[j]    * wr;
    m1 += r_emb[kH+j] * wr;
    w1 += WentW[k*kH+j];
  }
  g_Mr[k]=m0; g_Mr[kH+k]=m1; g_W1[k]=w1;
}

// ---------------- K2: entity timing tables ----------------
__global__ void k_tables(const int* __restrict__ eids, const float* __restrict__ dist0){
  const int e = threadIdx.x;   // 64 threads
  float curt = dist0[e];
  int cidx = -1, cnt = 0;
  for (int t=0;t<kT;t++){
    g_lastt[t*kE+e] = curt;
    g_eidx [t*kE+e] = cidx;
    if (eids[t]==e){ curt=(float)t; cidx=t; g_slist[e*kT+cnt]=t; cnt++; }
  }
  g_scnt[e]=cnt;
}

// ---------------- K3: X = W_ih @ emb[tok] + b_ih + b_hh ----------------
__global__ void __launch_bounds__(128)
k_xgemm(const int* __restrict__ toks_g, const float* __restrict__ emb,
        const float* __restrict__ Wih, const float* __restrict__ bih,
        const float* __restrict__ bhh){
  __shared__ int   toks[32];
  __shared__ float As[32][33];
  __shared__ float Ws[128][33];
  const int tid = threadIdx.x;
  const int rb  = blockIdx.x*128;   // gate rows
  const int t0  = blockIdx.y*32;    // timesteps
  if (tid<32) toks[tid] = toks_g[t0+tid];
  __syncthreads();
  float acc[32];
  #pragma unroll
  for (int i=0;i<32;i++) acc[i]=0.f;
  for (int kc=0;kc<kH;kc+=32){
    for (int i=tid;i<1024;i+=128) As[i>>5][i&31] = emb[toks[i>>5]*kH + kc + (i&31)];
    for (int i=tid;i<4096;i+=128) Ws[i>>5][i&31] = Wih[(rb+(i>>5))*kH + kc + (i&31)];
    __syncthreads();
    #pragma unroll 8
    for (int kk=0;kk<32;kk++){
      float wv = Ws[tid][kk];
      #pragma unroll
      for (int ti=0;ti<32;ti++) acc[ti] += wv*As[ti][kk];
    }
    __syncthreads();
  }
  const int r = rb + tid;
  const float bb = bih[r] + bhh[r];
  #pragma unroll
  for (int ti=0;ti<32;ti++) g_X[(t0+ti)*kG + r] = acc[ti] + bb;
}

// ---------------- generic: out[t][r] = sum_k W[r][k]*A[t][k] (+bias[r]) (+add[t][r]) ----------------
__global__ void __launch_bounds__(128)
k_gemvT(const float* __restrict__ A, const float* __restrict__ W,
        float* __restrict__ out, const float* __restrict__ bias,
        const float* __restrict__ add){
  __shared__ float As[32][33];
  __shared__ float Ws[128][33];
  const int tid = threadIdx.x;
  const int rb  = blockIdx.x*128;
  const int t0  = blockIdx.y*32;
  float acc[32];
  #pragma unroll
  for (int i=0;i<32;i++) acc[i]=0.f;
  for (int kc=0;kc<kH;kc+=32){
    for (int i=tid;i<1024;i+=128) As[i>>5][i&31] = A[(t0+(i>>5))*kH + kc + (i&31)];
    for (int i=tid;i<4096;i+=128) Ws[i>>5][i&31] = W[(rb+(i>>5))*kH + kc + (i&31)];
    __syncthreads();
    #pragma unroll 8
    for (int kk=0;kk<32;kk++){
      float wv = Ws[tid][kk];
      #pragma unroll
      for (int ti=0;ti<32;ti++) acc[ti] += wv*As[ti][kk];
    }
    __syncthreads();
  }
  const int r = rb + tid;
  const float b = bias ? bias[r] : 0.f;
  #pragma unroll
  for (int ti=0;ti<32;ti++){
    float v = acc[ti] + b;
    if (add) v += add[(t0+ti)*kH + r];
    out[(t0+ti)*kH + r] = v;
  }
}

// ---------------- K4: sequential LSTM, 8-CTA cluster, warp-self-contained ----------------
// Warp w, lane l: half=l>>4, gate=(l&15)>>2, rowid=w*4+(l&3).
// Gate row: row_g = gate*256 + c*32 + rowid. Cross-half reduce via shfl_xor(16),
// gate gather via 3 shfl, nonlin+broadcast in lanes 0..3. NO CTA barriers in loop:
// correctness invariant = mbar[buf] completion implies every warp of every CTA
// passed its step-t store, hence finished its step-t reads of h_s[buf^1].
__global__ void __cluster_dims__(8,1,1) __launch_bounds__(256,1)
k_lstm(const float* __restrict__ Whh){
  __shared__ float h_s[2][kH];                 // double-buffered h
  __shared__ __align__(8) unsigned long long mbar[2];
  const int tid  = threadIdx.x;
  const int w    = tid >> 5;
  const int lane = tid & 31;
  const int half = lane >> 4;
  const int sub  = lane & 15;
  const int gate = sub >> 2;
  const int ir   = sub & 3;
  unsigned rank; asm("mov.u32 %0, %%cluster_ctarank;" : "=r"(rank));
  const int c = (int)rank;
  const int row_g = gate*256 + c*32 + w*4 + ir;

  // my 128 weights as 64 packed float2
  const unsigned long long* wp = (const unsigned long long*)(Whh + row_g*kH + half*128);
  unsigned long long wreg[64];
  #pragma unroll
  for (int i=0;i<64;i++) wreg[i] = wp[i];

  ((float*)h_s)[tid]       = 0.f;
  ((float*)h_s)[tid + 256] = 0.f;              // h(-1) = 0 in buffer 1
  if (tid==0){
    mbar_init(smem_u32(&mbar[0]), 1);
    mbar_init(smem_u32(&mbar[1]), 1);
  }
  __syncthreads();
  asm volatile("barrier.cluster.arrive.aligned;" ::: "memory");
  asm volatile("barrier.cluster.wait.aligned;"   ::: "memory");

  // nonlin lanes (lane<4): this thread's h element
  const int ii = lane & 3;
  const int kk = c*32 + w*4 + ii;
  unsigned rh[8], rmb[8];
  {
    unsigned lh = smem_u32(&h_s[0][kk]);
    unsigned lm = smem_u32(&mbar[0]);
    #pragma unroll
    for (int rk=0; rk<8; rk++){
      asm("mapa.shared::cluster.u32 %0, %1, %2;" : "=r"(rh[rk])  : "r"(lh), "r"(rk));
      asm("mapa.shared::cluster.u32 %0, %1, %2;" : "=r"(rmb[rk]) : "r"(lm), "r"(rk));
    }
  }
  const unsigned lmb = smem_u32(&mbar[0]);

  float c_r = 0.f;
  float xv  = g_X[row_g];                      // prefetch t=0
  int ph0 = 0, ph1 = 0;

  for (int t=0; t<kT; t++){
    const int buf  = t & 1;
    const int pbuf = buf ^ 1;

    if (tid==0) mbar_expect(lmb + (unsigned)buf*8u, 1024u);

    // matvec over h(t-1)
    const ulonglong2* hb = (const ulonglong2*)&h_s[pbuf][half*128];
    unsigned long long acc_a = 0ull, acc_b = 0ull;
    #pragma unroll
    for (int q=0;q<32;q++){
      ulonglong2 hv = hb[q];
      fma2(acc_a, wreg[2*q],   hv.x);
      fma2(acc_b, wreg[2*q+1], hv.y);
    }
    float a0,a1,b0,b1; upk2(acc_a,a0,a1); upk2(acc_b,b0,b1);
    float s = (a0+a1)+(b0+b1);
    s += __shfl_xor_sync(0xffffffffu, s, 16);   // combine halves
    float gvv = s + xv;
    if (t+1 < kT) xv = g_X[(t+1)*kG + row_g];   // prefetch next x

    // gather i,f,g,o for element ii (valid in lanes 0..3)
    float gi = __shfl_sync(0xffffffffu, gvv, ii);
    float gf = __shfl_sync(0xffffffffu, gvv, 4+ii);
    float gg = __shfl_sync(0xffffffffu, gvv, 8+ii);
    float go = __shfl_sync(0xffffffffu, gvv, 12+ii);

    if (lane < 4){
      c_r = fsig(gf)*c_r + fsig(gi)*ftanh(gg);
      float hn = fsig(go)*ftanh(c_r);
      g_H[t*kH + kk] = hn;
      #pragma unroll
      for (int rk=0; rk<8; rk++)
        st_async_remote(rh[rk] + (unsigned)buf*1024u, hn, rmb[rk] + (unsigned)buf*8u);
    }

    if (buf==0){ mbar_waitp(lmb,      (unsigned)ph0); ph0 ^= 1; }
    else       { mbar_waitp(lmb + 8u, (unsigned)ph1); ph1 ^= 1; }
  }

  asm volatile("barrier.cluster.arrive.aligned;" ::: "memory");
  asm volatile("barrier.cluster.wait.aligned;"   ::: "memory");
}

// ---------------- K5: entity chains (one warp per entity) ----------------
__global__ void __launch_bounds__(32)
k_entity(const float* __restrict__ ents0, const float* __restrict__ Wdelta_b){
  const int e    = blockIdx.x;
  const int lane = threadIdx.x;
  const float db = Wdelta_b[0];
  float val[8];
  #pragma unroll
  for (int q=0;q<8;q++) val[q] = ents0[e*kH + q*32 + lane];

  const int n = g_scnt[e];
  for (int s=0;s<n;s++){
    const int t = g_slist[e*kT+s];
    float d1 = 0.f;
    #pragma unroll
    for (int q=0;q<8;q++){
      const int k = q*32+lane;
      g_Ec[t*kH+k] = val[q];
      d1 += val[q]*g_Gd[t*kH+k];
    }
    d1 = wred(d1);
    const float delta = sigf(d1 + db);
    float ss = 0.f;
    float u[8];
    #pragma unroll
    for (int q=0;q<8;q++){
      const int k = q*32+lane;
      u[q] = delta*val[q] + (1.f-delta)*g_H[t*kH+k];
      ss += u[q]*u[q];
    }
    ss = wred(ss);
    const float inv = 1.0f/sqrtf(ss);
    #pragma unroll
    for (int q=0;q<8;q++){
      val[q] = u[q]*inv;
      g_U[t*kH + q*32 + lane] = val[q];
    }
  }
}

// ---------------- K6: small heads (pred_r, pred_e, pred_l) ----------------
__global__ void __launch_bounds__(128)
k_heads(float* __restrict__ out,
        const float* __restrict__ Wr_b,   const float* __restrict__ WlenW,
        const float* __restrict__ Wlen_b, const float* __restrict__ Went_b,
        const float* __restrict__ wdW,    const float* __restrict__ wdb,
        const float* __restrict__ ents0){
  __shared__ float hs[kH], ges[kH], ecs[kH], w1s[kH];
  const int t    = blockIdx.x;
  const int tid  = threadIdx.x;
  const int warp = tid>>5, lane = tid&31;
  hs [tid]=g_H [t*kH+tid]; hs [tid+128]=g_H [t*kH+tid+128];
  ges[tid]=g_Ge[t*kH+tid]; ges[tid+128]=g_Ge[t*kH+tid+128];
  ecs[tid]=g_Ec[t*kH+tid]; ecs[tid+128]=g_Ec[t*kH+tid+128];
  w1s[tid]=g_W1[tid];      w1s[tid+128]=g_W1[tid+128];
  __syncthreads();
  float* orow = out + (size_t)t*kOW;

  // pred_r (warps 0,1)
  if (warp < 2){
    float s = 0.f;
    #pragma unroll
    for (int q=0;q<8;q++){ int k=q*32+lane; s += g_Mr[warp*kH+k]*hs[k]; }
    s = wred(s);
    if (lane==0) orow[warp] = s + Wr_b[0];
  }
  // pred_l (all warps, rows strided by 4)
  for (int r=warp; r<25; r+=4){
    float s = 0.f;
    #pragma unroll
    for (int q=0;q<16;q++){
      int k = q*32+lane;
      float xk = (k<kH) ? hs[k] : ecs[k-kH];
      s += WlenW[r*(2*kH)+k]*xk;
    }
    s = wred(s);
    if (lane==0) orow[66+r] = s + Wlen_b[r];
  }
  // pred_e (16 entities per warp)
  const float tf = (float)t;
  const float wdw = wdW[0], wdbv = wdb[0], geb = Went_b[0];
  for (int ei=0; ei<16; ei++){
    const int e = warp*16 + ei;
    const int ix = g_eidx[t*kE+e];
    const float* ep = (ix < 0) ? (ents0 + e*kH) : (g_U + (size_t)ix*kH);
    float s1=0.f, s2=0.f;
    #pragma unroll
    for (int q=0;q<8;q++){
      int k=q*32+lane;
      float ev = ep[k];
      s1 += ev*ges[k];
      s2 += ev*w1s[k];
    }
    s1 = wred(s1); s2 = wred(s2);
    if (lane==0){
      float dist = g_lastt[t*kE+e] - tf;
      float sc = dist*wdw + wdbv;
      orow[2+e] = s1 + sc*s2 + geb;
    }
  }
}

// ---------------- K7: logits GEMM  out[t][91+v] = Vv[t]·outW[v] + outb[v] ----------------
#define BM 128
#define BN 128
#define BK 32
__global__ void __launch_bounds__(256,2)
k_logits(const float* __restrict__ outW, const float* __restrict__ outb,
         float* __restrict__ out){
  __shared__ float As[BK][BM+4];
  __shared__ float Bs[BK][BN+4];
  const int tid = threadIdx.x;
  const int n0 = blockIdx.x*BN;
  const int m0 = blockIdx.y*BM;
  const int tx = tid&15, ty = tid>>4;

  unsigned long long acc[4][8];
  #pragma unroll
  for (int i=0;i<4;i++)
    #pragma unroll
    for (int jj=0;jj<8;jj++) acc[i][jj]=0ull;

  for (int kc=0; kc<kH; kc+=BK){
    #pragma unroll
    for (int l=0;l<4;l++){
      int idx = tid + 256*l;          // 0..1023
      int row = idx>>3;
      int kq  = idx&7;
      // A tile
      float4 av = *(const float4*)&g_Vv[(m0+row)*kH + kc + kq*4];
      As[kq*4+0][row]=av.x; As[kq*4+1][row]=av.y; As[kq*4+2][row]=av.z; As[kq*4+3][row]=av.w;
      // B tile (guard vocab edge)
      int v = n0 + row;
      float4 bv = make_float4(0.f,0.f,0.f,0.f);
      if (v < kV) bv = *(const float4*)&outW[v*kH + kc + kq*4];
      Bs[kq*4+0][row]=bv.x; Bs[kq*4+1][row]=bv.y; Bs[kq*4+2][row]=bv.z; Bs[kq*4+3][row]=bv.w;
    }
    __syncthreads();
    #pragma unroll
    for (int k=0;k<BK;k++){
      float4 a0 = *(const float4*)&As[k][ty*8];
      float4 a1 = *(const float4*)&As[k][ty*8+4];
      unsigned long long ap[4];
      ap[0]=pk2(a0.x,a0.y); ap[1]=pk2(a0.z,a0.w);
      ap[2]=pk2(a1.x,a1.y); ap[3]=pk2(a1.z,a1.w);
      float4 b0 = *(const float4*)&Bs[k][tx*8];
      float4 b1 = *(const float4*)&Bs[k][tx*8+4];
      unsigned long long bb[8];
      bb[0]=pk2(b0.x,b0.x); bb[1]=pk2(b0.y,b0.y); bb[2]=pk2(b0.z,b0.z); bb[3]=pk2(b0.w,b0.w);
      bb[4]=pk2(b1.x,b1.x); bb[5]=pk2(b1.y,b1.y); bb[6]=pk2(b1.z,b1.z); bb[7]=pk2(b1.w,b1.w);
      #pragma unroll
      for (int ip=0; ip<4; ip++)
        #pragma unroll
        for (int jj=0; jj<8; jj++)
          fma2(acc[ip][jj], ap[ip], bb[jj]);
    }
    __syncthreads();
  }

  const int c0 = n0 + tx*8;
  float bvals[8];
  #pragma unroll
  for (int jj=0;jj<8;jj++) bvals[jj] = (c0+jj < kV) ? outb[c0+jj] : 0.f;
  #pragma unroll
  for (int ip=0; ip<4; ip++){
    const int r0 = m0 + ty*8 + 2*ip;
    float* o0 = out + (size_t)r0*kOW + 91 + c0;
    float* o1 = o0 + kOW;
    #pragma unroll
    for (int jj=0;jj<8;jj++){
      if (c0+jj < kV){
        float lo,hi; upk2(acc[ip][jj], lo, hi);
        o0[jj] = lo + bvals[jj];
        o1[jj] = hi + bvals[jj];
      }
    }
  }
}

// ---------------- launch ----------------
extern "C" void kernel_launch(void* const* d_in, const int* in_sizes, int n_in,
                              void* d_out, int out_size){
  const int*   tokens  = (const int*)  d_in[0];
  const int*   eids    = (const int*)  d_in[1];
  const float* emb     = (const float*)d_in[2];
  const float* W_ih    = (const float*)d_in[3];
  const float* W_hh    = (const float*)d_in[4];
  const float* b_ih    = (const float*)d_in[5];
  const float* b_hh    = (const float*)d_in[6];
  const float* out_W   = (const float*)d_in[7];
  const float* out_b   = (const float*)d_in[8];
  const float* r_emb   = (const float*)d_in[9];
  const float* Wr_W    = (const float*)d_in[10];
  const float* Wr_b    = (const float*)d_in[11];
  const float* Wlen_W  = (const float*)d_in[12];
  const float* Wlen_b  = (const float*)d_in[13];
  const float* Went_W  = (const float*)d_in[14];
  const float* Went_b  = (const float*)d_in[15];
  const float* wdist_W = (const float*)d_in[16];
  const float* wdist_b = (const float*)d_in[17];
  const float* Wdelta_W= (const float*)d_in[18];
  const float* Wdelta_b= (const float*)d_in[19];
  const float* We_W    = (const float*)d_in[20];
  const float* We_b    = (const float*)d_in[21];
  const float* ents0   = (const float*)d_in[22];
  const float* dist0   = (const float*)d_in[23];
  float* out = (float*)d_out;

  float *gX, *gH, *gGd, *gGe, *gU, *gEc, *gVv;
  cudaGetSymbolAddress((void**)&gX,  g_X);
  cudaGetSymbolAddress((void**)&gH,  g_H);
  cudaGetSymbolAddress((void**)&gGd, g_Gd);
  cudaGetSymbolAddress((void**)&gGe, g_Ge);
  cudaGetSymbolAddress((void**)&gU,  g_U);
  cudaGetSymbolAddress((void**)&gEc, g_Ec);
  cudaGetSymbolAddress((void**)&gVv, g_Vv);

  k_prep  <<<1, 256>>>(r_emb, Wr_W, Went_W);
  k_tables<<<1, 64>>>(eids, dist0);
  k_xgemm <<<dim3(8,64), 128>>>(tokens, emb, W_ih, b_ih, b_hh);
  k_lstm  <<<8, 256>>>(W_hh);
  k_gemvT <<<dim3(2,64), 128>>>(gH,  Wdelta_W, gGd, (const float*)0, (const float*)0);
  k_gemvT <<<dim3(2,64), 128>>>(gH,  Went_W,   gGe, (const float*)0, (const float*)0);
  k_entity<<<64, 32>>>(ents0, Wdelta_b);
  k_gemvT <<<dim3(2,64), 128>>>(gEc, We_W,     gVv, We_b, gH);
  k_heads <<<kT, 128>>>(out, Wr_b, Wlen_W, Wlen_b, Went_b, wdist_W, wdist_b, ents0);
  k_logits<<<dim3((kV+BN-1)/BN, kT/BM), 256>>>(out_W, out_b, out);
}

// round 8
// speedup vs baseline: 1.6438x; 1.2664x over previous
#include <cuda_runtime.h>
#include <cuda_bf16.h>
#include <math.h>

#define kT   2048
#define kH   256
#define kE   64
#define kV   50257
#define kG   1024
#define kOW  50348   /* 2 + 64 + 25 + 50257 */

// ---------------- scratch (static device globals; no allocation) ----------------
__device__ float g_X [kT*kG];   // W_ih@emb[tok] + b_ih + b_hh
__device__ float g_H [kT*kH];   // h_t
__device__ float g_Gd[kT*kH];   // Wdelta @ h_t
__device__ float g_Ge[kT*kH];   // Went   @ h_t
__device__ float g_U [kT*kH];   // post-update entity vec at step t
__device__ float g_Ec[kT*kH];   // e_cur (pre-update) at step t
__device__ float g_Vv[kT*kH];   // h + We@e_cur + We_b
__device__ float g_Mr[2*kH];    // r_emb @ Wr_W
__device__ float g_W1[kH];      // row sums of Went
__device__ float g_lastt[kT*kE];
__device__ int   g_eidx [kT*kE];
__device__ int   g_slist[kE*kT];
__device__ int   g_scnt [kE];
// bf16 splits for tensor-core logits
__device__ __nv_bfloat16 g_Whi[kV*kH];
__device__ __nv_bfloat16 g_Wlo[kV*kH];
__device__ __nv_bfloat16 g_Vhi[kT*kH];
__device__ __nv_bfloat16 g_Vlo[kT*kH];

// ---------------- helpers ----------------
__device__ __forceinline__ float sigf(float x){ return 1.0f/(1.0f+expf(-x)); }
__device__ __forceinline__ float fsig(float x){ return __fdividef(1.0f, 1.0f + __expf(-x)); }
__device__ __forceinline__ float ftanh(float x){ return __fdividef(2.0f, 1.0f + __expf(-2.0f*x)) - 1.0f; }

__device__ __forceinline__ void fma2(unsigned long long &d, unsigned long long a, unsigned long long b){
  asm("fma.rn.f32x2 %0, %1, %2, %0;" : "+l"(d) : "l"(a), "l"(b));
}
__device__ __forceinline__ void upk2(unsigned long long v, float &lo, float &hi){
  asm("mov.b64 {%0,%1}, %2;" : "=f"(lo), "=f"(hi) : "l"(v));
}
__device__ __forceinline__ unsigned smem_u32(const void* p){
  unsigned r;
  asm("{ .reg .u64 t; cvta.to.shared.u64 t, %1; cvt.u32.u64 %0, t; }" : "=r"(r) : "l"(p));
  return r;
}
__device__ __forceinline__ float wred(float v){
  #pragma unroll
  for (int o=16;o;o>>=1) v += __shfl_xor_sync(0xffffffffu, v, o);
  return v;
}
__device__ __forceinline__ void mbar_init(unsigned a, unsigned cnt){
  asm volatile("mbarrier.init.shared.b64 [%0], %1;" :: "r"(a), "r"(cnt) : "memory");
}
__device__ __forceinline__ void mbar_expect(unsigned a, unsigned tx){
  asm volatile("mbarrier.arrive.expect_tx.shared.b64 _, [%0], %1;" :: "r"(a), "r"(tx) : "memory");
}
__device__ __forceinline__ void mbar_waitp(unsigned a, unsigned ph){
  unsigned done;
  asm volatile("{\n\t.reg .pred p;\n\t"
               "mbarrier.try_wait.parity.acquire.cluster.shared::cta.b64 p, [%1], %2;\n\t"
               "selp.b32 %0, 1, 0, p;\n\t}"
               : "=r"(done) : "r"(a), "r"(ph) : "memory");
  if (!done){
    asm volatile("{\n\t.reg .pred P1;\n\t"
                 "WL_%=:\n\t"
                 "mbarrier.try_wait.parity.acquire.cluster.shared::cta.b64 P1, [%0], %1, 0x989680;\n\t"
                 "@P1 bra.uni WD_%=;\n\t"
                 "bra.uni WL_%=;\n\t"
                 "WD_%=:\n\t}"
                 :: "r"(a), "r"(ph) : "memory");
  }
}
__device__ __forceinline__ void st_async_remote(unsigned dst, float v, unsigned mb){
  asm volatile("st.async.shared::cluster.mbarrier::complete_tx::bytes.u32 [%0], %1, [%2];"
               :: "r"(dst), "r"(__float_as_uint(v)), "r"(mb) : "memory");
}

// ---------------- K1: tiny precomputes ----------------
__global__ void k_prep(const float* __restrict__ r_emb,
                       const float* __restrict__ WrW,
                       const float* __restrict__ WentW){
  const int k = threadIdx.x;   // 256 threads
  float m0=0.f, m1=0.f, w1=0.f;
  for (int j=0;j<kH;j++){
    float wr = WrW[j*kH+k];
    m0 += r_emb[j]    * wr;
    m1 += r_emb[kH+j] * wr;
    w1 += WentW[k*kH+j];
  }
  g_Mr[k]=m0; g_Mr[kH+k]=m1; g_W1[k]=w1;
}

// ---------------- K2: entity timing tables ----------------
__global__ void k_tables(const int* __restrict__ eids, const float* __restrict__ dist0){
  const int e = threadIdx.x;   // 64 threads
  float curt = dist0[e];
  int cidx = -1, cnt = 0;
  for (int t=0;t<kT;t++){
    g_lastt[t*kE+e] = curt;
    g_eidx [t*kE+e] = cidx;
    if (eids[t]==e){ curt=(float)t; cidx=t; g_slist[e*kT+cnt]=t; cnt++; }
  }
  g_scnt[e]=cnt;
}

// ---------------- bf16 hi/lo split ----------------
__global__ void k_split(const float* __restrict__ src,
                        __nv_bfloat16* __restrict__ hi,
                        __nv_bfloat16* __restrict__ lo, int n){
  int i = blockIdx.x*256 + threadIdx.x;
  if (i < n){
    float w = src[i];
    __nv_bfloat16 h = __float2bfloat16(w);
    hi[i] = h;
    lo[i] = __float2bfloat16(w - __bfloat162float(h));
  }
}

// ---------------- K3: X = W_ih @ emb[tok] + b_ih + b_hh ----------------
__global__ void __launch_bounds__(128)
k_xgemm(const int* __restrict__ toks_g, const float* __restrict__ emb,
        const float* __restrict__ Wih, const float* __restrict__ bih,
        const float* __restrict__ bhh){
  __shared__ int   toks[32];
  __shared__ float As[32][33];
  __shared__ float Ws[128][33];
  const int tid = threadIdx.x;
  const int rb  = blockIdx.x*128;   // gate rows
  const int t0  = blockIdx.y*32;    // timesteps
  if (tid<32) toks[tid] = toks_g[t0+tid];
  __syncthreads();
  float acc[32];
  #pragma unroll
  for (int i=0;i<32;i++) acc[i]=0.f;
  for (int kc=0;kc<kH;kc+=32){
    for (int i=tid;i<1024;i+=128) As[i>>5][i&31] = emb[toks[i>>5]*kH + kc + (i&31)];
    for (int i=tid;i<4096;i+=128) Ws[i>>5][i&31] = Wih[(rb+(i>>5))*kH + kc + (i&31)];
    __syncthreads();
    #pragma unroll 8
    for (int kk=0;kk<32;kk++){
      float wv = Ws[tid][kk];
      #pragma unroll
      for (int ti=0;ti<32;ti++) acc[ti] += wv*As[ti][kk];
    }
    __syncthreads();
  }
  const int r = rb + tid;
  const float bb = bih[r] + bhh[r];
  #pragma unroll
  for (int ti=0;ti<32;ti++) g_X[(t0+ti)*kG + r] = acc[ti] + bb;
}

// ---------------- generic: out[t][r] = sum_k W[r][k]*A[t][k] (+bias[r]) (+add[t][r]) ----------------
__global__ void __launch_bounds__(128)
k_gemvT(const float* __restrict__ A, const float* __restrict__ W,
        float* __restrict__ out, const float* __restrict__ bias,
        const float* __restrict__ add){
  __shared__ float As[32][33];
  __shared__ float Ws[128][33];
  const int tid = threadIdx.x;
  const int rb  = blockIdx.x*128;
  const int t0  = blockIdx.y*32;
  float acc[32];
  #pragma unroll
  for (int i=0;i<32;i++) acc[i]=0.f;
  for (int kc=0;kc<kH;kc+=32){
    for (int i=tid;i<1024;i+=128) As[i>>5][i&31] = A[(t0+(i>>5))*kH + kc + (i&31)];
    for (int i=tid;i<4096;i+=128) Ws[i>>5][i&31] = W[(rb+(i>>5))*kH + kc + (i&31)];
    __syncthreads();
    #pragma unroll 8
    for (int kk=0;kk<32;kk++){
      float wv = Ws[tid][kk];
      #pragma unroll
      for (int ti=0;ti<32;ti++) acc[ti] += wv*As[ti][kk];
    }
    __syncthreads();
  }
  const int r = rb + tid;
  const float b = bias ? bias[r] : 0.f;
  #pragma unroll
  for (int ti=0;ti<32;ti++){
    float v = acc[ti] + b;
    if (add) v += add[(t0+ti)*kH + r];
    out[(t0+ti)*kH + r] = v;
  }
}

// ---------------- K4: sequential LSTM, 8-CTA cluster, warp-self-contained ----------------
// Warp w, lane l: half=l>>4, gate=(l&15)>>2, rowid=w*4+(l&3).
// All 32 lanes redundantly compute the nonlinearity for element ii=l&3 and each
// lane issues exactly ONE st.async to rank l>>2 (parallel issue, 1/warp).
__global__ void __cluster_dims__(8,1,1) __launch_bounds__(256,1)
k_lstm(const float* __restrict__ Whh){
  __shared__ float h_s[2][kH];                 // double-buffered h
  __shared__ __align__(8) unsigned long long mbar[2];
  const int tid  = threadIdx.x;
  const int w    = tid >> 5;
  const int lane = tid & 31;
  const int half = lane >> 4;
  const int sub  = lane & 15;
  const int gate = sub >> 2;
  const int ir   = sub & 3;
  unsigned rank; asm("mov.u32 %0, %%cluster_ctarank;" : "=r"(rank));
  const int c = (int)rank;
  const int row_g = gate*256 + c*32 + w*4 + ir;

  // my 128 weights as 64 packed float2
  const unsigned long long* wp = (const unsigned long long*)(Whh + row_g*kH + half*128);
  unsigned long long wreg[64];
  #pragma unroll
  for (int i=0;i<64;i++) wreg[i] = wp[i];

  ((float*)h_s)[tid]       = 0.f;
  ((float*)h_s)[tid + 256] = 0.f;              // h(-1) = 0 in buffer 1
  if (tid==0){
    mbar_init(smem_u32(&mbar[0]), 1);
    mbar_init(smem_u32(&mbar[1]), 1);
  }
  __syncthreads();
  asm volatile("barrier.cluster.arrive.aligned;" ::: "memory");
  asm volatile("barrier.cluster.wait.aligned;"   ::: "memory");

  // this lane's (element, destination-rank) pair
  const int ii     = lane & 3;
  const int rank_d = lane >> 2;
  const int kk     = c*32 + w*4 + ii;
  unsigned rh, rmb;
  {
    unsigned lh = smem_u32(&h_s[0][kk]);
    unsigned lm = smem_u32(&mbar[0]);
    asm("mapa.shared::cluster.u32 %0, %1, %2;" : "=r"(rh)  : "r"(lh), "r"(rank_d));
    asm("mapa.shared::cluster.u32 %0, %1, %2;" : "=r"(rmb) : "r"(lm), "r"(rank_d));
  }
  const unsigned lmb = smem_u32(&mbar[0]);

  float c_r = 0.f;
  float xv  = g_X[row_g];                      // prefetch t=0
  int ph0 = 0, ph1 = 0;

  for (int t=0; t<kT; t++){
    const int buf  = t & 1;
    const int pbuf = buf ^ 1;

    if (tid==0) mbar_expect(lmb + (unsigned)buf*8u, 1024u);

    // matvec over h(t-1)
    const ulonglong2* hb = (const ulonglong2*)&h_s[pbuf][half*128];
    unsigned long long acc_a = 0ull, acc_b = 0ull;
    #pragma unroll
    for (int q=0;q<32;q++){
      ulonglong2 hv = hb[q];
      fma2(acc_a, wreg[2*q],   hv.x);
      fma2(acc_b, wreg[2*q+1], hv.y);
    }
    float a0,a1,b0,b1; upk2(acc_a,a0,a1); upk2(acc_b,b0,b1);
    float s = (a0+a1)+(b0+b1);
    s += __shfl_xor_sync(0xffffffffu, s, 16);   // combine halves
    float gvv = s + xv;
    if (t+1 < kT) xv = g_X[(t+1)*kG + row_g];   // prefetch next x

    // gather i,f,g,o for element ii (all lanes, redundant across rank_d)
    float gi = __shfl_sync(0xffffffffu, gvv, ii);
    float gf = __shfl_sync(0xffffffffu, gvv, 4+ii);
    float gg = __shfl_sync(0xffffffffu, gvv, 8+ii);
    float go = __shfl_sync(0xffffffffu, gvv, 12+ii);

    c_r = fsig(gf)*c_r + fsig(gi)*ftanh(gg);
    float hn = fsig(go)*ftanh(c_r);
    if (lane < 4) g_H[t*kH + kk] = hn;
    st_async_remote(rh + (unsigned)buf*1024u, hn, rmb + (unsigned)buf*8u);

    if (buf==0){ mbar_waitp(lmb,      (unsigned)ph0); ph0 ^= 1; }
    else       { mbar_waitp(lmb + 8u, (unsigned)ph1); ph1 ^= 1; }
  }

  asm volatile("barrier.cluster.arrive.aligned;" ::: "memory");
  asm volatile("barrier.cluster.wait.aligned;"   ::: "memory");
}

// ---------------- K5: entity chains (one warp per entity) ----------------
__global__ void __launch_bounds__(32)
k_entity(const float* __restrict__ ents0, const float* __restrict__ Wdelta_b){
  const int e    = blockIdx.x;
  const int lane = threadIdx.x;
  const float db = Wdelta_b[0];
  float val[8];
  #pragma unroll
  for (int q=0;q<8;q++) val[q] = ents0[e*kH + q*32 + lane];

  const int n = g_scnt[e];
  for (int s=0;s<n;s++){
    const int t = g_slist[e*kT+s];
    float d1 = 0.f;
    #pragma unroll
    for (int q=0;q<8;q++){
      const int k = q*32+lane;
      g_Ec[t*kH+k] = val[q];
      d1 += val[q]*g_Gd[t*kH+k];
    }
    d1 = wred(d1);
    const float delta = sigf(d1 + db);
    float ss = 0.f;
    float u[8];
    #pragma unroll
    for (int q=0;q<8;q++){
      const int k = q*32+lane;
      u[q] = delta*val[q] + (1.f-delta)*g_H[t*kH+k];
      ss += u[q]*u[q];
    }
    ss = wred(ss);
    const float inv = 1.0f/sqrtf(ss);
    #pragma unroll
    for (int q=0;q<8;q++){
      val[q] = u[q]*inv;
      g_U[t*kH + q*32 + lane] = val[q];
    }
  }
}

// ---------------- K6: small heads (pred_r, pred_e, pred_l) ----------------
__global__ void __launch_bounds__(128)
k_heads(float* __restrict__ out,
        const float* __restrict__ Wr_b,   const float* __restrict__ WlenW,
        const float* __restrict__ Wlen_b, const float* __restrict__ Went_b,
        const float* __restrict__ wdW,    const float* __restrict__ wdb,
        const float* __restrict__ ents0){
  __shared__ float hs[kH], ges[kH], ecs[kH], w1s[kH];
  const int t    = blockIdx.x;
  const int tid  = threadIdx.x;
  const int warp = tid>>5, lane = tid&31;
  hs [tid]=g_H [t*kH+tid]; hs [tid+128]=g_H [t*kH+tid+128];
  ges[tid]=g_Ge[t*kH+tid]; ges[tid+128]=g_Ge[t*kH+tid+128];
  ecs[tid]=g_Ec[t*kH+tid]; ecs[tid+128]=g_Ec[t*kH+tid+128];
  w1s[tid]=g_W1[tid];      w1s[tid+128]=g_W1[tid+128];
  __syncthreads();
  float* orow = out + (size_t)t*kOW;

  // pred_r (warps 0,1)
  if (warp < 2){
    float s = 0.f;
    #pragma unroll
    for (int q=0;q<8;q++){ int k=q*32+lane; s += g_Mr[warp*kH+k]*hs[k]; }
    s = wred(s);
    if (lane==0) orow[warp] = s + Wr_b[0];
  }
  // pred_l (all warps, rows strided by 4)
  for (int r=warp; r<25; r+=4){
    float s = 0.f;
    #pragma unroll
    for (int q=0;q<16;q++){
      int k = q*32+lane;
      float xk = (k<kH) ? hs[k] : ecs[k-kH];
      s += WlenW[r*(2*kH)+k]*xk;
    }
    s = wred(s);
    if (lane==0) orow[66+r] = s + Wlen_b[r];
  }
  // pred_e (16 entities per warp)
  const float tf = (float)t;
  const float wdw = wdW[0], wdbv = wdb[0], geb = Went_b[0];
  for (int ei=0; ei<16; ei++){
    const int e = warp*16 + ei;
    const int ix = g_eidx[t*kE+e];
    const float* ep = (ix < 0) ? (ents0 + e*kH) : (g_U + (size_t)ix*kH);
    float s1=0.f, s2=0.f;
    #pragma unroll
    for (int q=0;q<8;q++){
      int k=q*32+lane;
      float ev = ep[k];
      s1 += ev*ges[k];
      s2 += ev*w1s[k];
    }
    s1 = wred(s1); s2 = wred(s2);
    if (lane==0){
      float dist = g_lastt[t*kE+e] - tf;
      float sc = dist*wdw + wdbv;
      orow[2+e] = s1 + sc*s2 + geb;
    }
  }
}

// ---------------- K7: logits via tensor cores (3-term bf16 split) ----------------
// out[t][91+v] = Vv[t]·outW[v] + outb[v]
// C += Ah*Bh + Ah*Bl + Al*Bh  with fp32 accumulators (mma.sync m16n8k16 bf16)
__global__ void __launch_bounds__(256)
k_logits_mma(const float* __restrict__ outb, float* __restrict__ out){
  __shared__ __nv_bfloat16 Ah[128][40], Al[128][40], Bh[128][40], Bl[128][40];
  const int tid  = threadIdx.x;
  const int lane = tid & 31;
  const int w    = tid >> 5;
  const int warp_m = w >> 2;       // 0..1  (64 rows each)
  const int warp_n = w & 3;        // 0..3  (32 cols each)
  const int m0 = blockIdx.y * 128;
  const int n0 = blockIdx.x * 128;

  float acc[4][4][4];
  #pragma unroll
  for (int a=0;a<4;a++)
    #pragma unroll
    for (int b=0;b<4;b++)
      #pragma unroll
      for (int cidx=0;cidx<4;cidx++) acc[a][b][cidx]=0.f;

  for (int kc=0; kc<kH; kc+=32){
    // ---- load tiles: 128 rows x 32 bf16 (= 4 chunks of 8 bf16) per array
    #pragma unroll
    for (int i=tid; i<512; i+=256){
      const int r  = i >> 2;
      const int c8 = (i & 3) * 8;
      *(uint4*)&Ah[r][c8] = *(const uint4*)&g_Vhi[(m0+r)*kH + kc + c8];
      *(uint4*)&Al[r][c8] = *(const uint4*)&g_Vlo[(m0+r)*kH + kc + c8];
      const int v = n0 + r;
      uint4 z = make_uint4(0u,0u,0u,0u);
      *(uint4*)&Bh[r][c8] = (v<kV) ? *(const uint4*)&g_Whi[(size_t)v*kH + kc + c8] : z;
      *(uint4*)&Bl[r][c8] = (v<kV) ? *(const uint4*)&g_Wlo[(size_t)v*kH + kc + c8] : z;
    }
    __syncthreads();

    #pragma unroll
    for (int ks=0; ks<32; ks+=16){
      // A fragments (x4 ldmatrix): grp = lane>>3
      unsigned ah[4][4], al[4][4];
      #pragma unroll
      for (int mi=0; mi<4; mi++){
        const int row = warp_m*64 + mi*16 + ((lane>>3)&1)*8 + (lane&7);
        const int col = ks + (lane>>4)*8;
        unsigned ad = smem_u32(&Ah[row][col]);
        asm volatile("ldmatrix.sync.aligned.m8n8.x4.shared.b16 {%0,%1,%2,%3}, [%4];"
                     : "=r"(ah[mi][0]),"=r"(ah[mi][1]),"=r"(ah[mi][2]),"=r"(ah[mi][3]) : "r"(ad));
        unsigned ad2 = smem_u32(&Al[row][col]);
        asm volatile("ldmatrix.sync.aligned.m8n8.x4.shared.b16 {%0,%1,%2,%3}, [%4];"
                     : "=r"(al[mi][0]),"=r"(al[mi][1]),"=r"(al[mi][2]),"=r"(al[mi][3]) : "r"(ad2));
      }
      // B fragments (x2 ldmatrix): lanes 0-15 supply addresses
      unsigned bh[4][2], bl[4][2];
      #pragma unroll
      for (int ni=0; ni<4; ni++){
        const int row = warp_n*32 + ni*8 + (lane&7);
        const int col = ks + ((lane>>3)&1)*8;
        unsigned bd = smem_u32(&Bh[row][col]);
        asm volatile("ldmatrix.sync.aligned.m8n8.x2.shared.b16 {%0,%1}, [%2];"
                     : "=r"(bh[ni][0]),"=r"(bh[ni][1]) : "r"(bd));
        unsigned bd2 = smem_u32(&Bl[row][col]);
        asm volatile("ldmatrix.sync.aligned.m8n8.x2.shared.b16 {%0,%1}, [%2];"
                     : "=r"(bl[ni][0]),"=r"(bl[ni][1]) : "r"(bd2));
      }
      // 3-term mma
      #pragma unroll
      for (int mi=0; mi<4; mi++){
        #pragma unroll
        for (int ni=0; ni<4; ni++){
          float* cc = acc[mi][ni];
          asm volatile("mma.sync.aligned.m16n8k16.row.col.f32.bf16.bf16.f32 "
                       "{%0,%1,%2,%3}, {%4,%5,%6,%7}, {%8,%9}, {%0,%1,%2,%3};"
                       : "+f"(cc[0]),"+f"(cc[1]),"+f"(cc[2]),"+f"(cc[3])
                       : "r"(ah[mi][0]),"r"(ah[mi][1]),"r"(ah[mi][2]),"r"(ah[mi][3]),
                         "r"(bh[ni][0]),"r"(bh[ni][1]));
          asm volatile("mma.sync.aligned.m16n8k16.row.col.f32.bf16.bf16.f32 "
                       "{%0,%1,%2,%3}, {%4,%5,%6,%7}, {%8,%9}, {%0,%1,%2,%3};"
                       : "+f"(cc[0]),"+f"(cc[1]),"+f"(cc[2]),"+f"(cc[3])
                       : "r"(ah[mi][0]),"r"(ah[mi][1]),"r"(ah[mi][2]),"r"(ah[mi][3]),
                         "r"(bl[ni][0]),"r"(bl[ni][1]));
          asm volatile("mma.sync.aligned.m16n8k16.row.col.f32.bf16.bf16.f32 "
                       "{%0,%1,%2,%3}, {%4,%5,%6,%7}, {%8,%9}, {%0,%1,%2,%3};"
                       : "+f"(cc[0]),"+f"(cc[1]),"+f"(cc[2]),"+f"(cc[3])
                       : "r"(al[mi][0]),"r"(al[mi][1]),"r"(al[mi][2]),"r"(al[mi][3]),
                         "r"(bh[ni][0]),"r"(bh[ni][1]));
        }
      }
    }
    __syncthreads();
  }

  // ---- epilogue: C + bias -> out
  #pragma unroll
  for (int mi=0; mi<4; mi++){
    const int r0 = m0 + warp_m*64 + mi*16 + (lane>>2);
    #pragma unroll
    for (int ni=0; ni<4; ni++){
      const int cb = n0 + warp_n*32 + ni*8 + (lane&3)*2;
      float* cc = acc[mi][ni];
      if (cb < kV){
        float b0v = outb[cb];
        float b1v = (cb+1 < kV) ? outb[cb+1] : 0.f;
        float* o0 = out + (size_t)r0*kOW + 91 + cb;
        float* o1 = out + (size_t)(r0+8)*kOW + 91 + cb;
        o0[0] = cc[0] + b0v;
        o1[0] = cc[2] + b0v;
        if (cb+1 < kV){
          o0[1] = cc[1] + b1v;
          o1[1] = cc[3] + b1v;
        }
      }
    }
  }
}

// ---------------- launch ----------------
extern "C" void kernel_launch(void* const* d_in, const int* in_sizes, int n_in,
                              void* d_out, int out_size){
  const int*   tokens  = (const int*)  d_in[0];
  const int*   eids    = (const int*)  d_in[1];
  const float* emb     = (const float*)d_in[2];
  const float* W_ih    = (const float*)d_in[3];
  const float* W_hh    = (const float*)d_in[4];
  const float* b_ih    = (const float*)d_in[5];
  const float* b_hh    = (const float*)d_in[6];
  const float* out_W   = (const float*)d_in[7];
  const float* out_b   = (const float*)d_in[8];
  const float* r_emb   = (const float*)d_in[9];
  const float* Wr_W    = (const float*)d_in[10];
  const float* Wr_b    = (const float*)d_in[11];
  const float* Wlen_W  = (const float*)d_in[12];
  const float* Wlen_b  = (const float*)d_in[13];
  const float* Went_W  = (const float*)d_in[14];
  const float* Went_b  = (const float*)d_in[15];
  const float* wdist_W = (const float*)d_in[16];
  const float* wdist_b = (const float*)d_in[17];
  const float* Wdelta_W= (const float*)d_in[18];
  const float* Wdelta_b= (const float*)d_in[19];
  const float* We_W    = (const float*)d_in[20];
  const float* We_b    = (const float*)d_in[21];
  const float* ents0   = (const float*)d_in[22];
  const float* dist0   = (const float*)d_in[23];
  float* out = (float*)d_out;

  float *gX, *gH, *gGd, *gGe, *gU, *gEc, *gVv;
  __nv_bfloat16 *gWhi, *gWlo, *gVhi, *gVlo;
  cudaGetSymbolAddress((void**)&gX,  g_X);
  cudaGetSymbolAddress((void**)&gH,  g_H);
  cudaGetSymbolAddress((void**)&gGd, g_Gd);
  cudaGetSymbolAddress((void**)&gGe, g_Ge);
  cudaGetSymbolAddress((void**)&gU,  g_U);
  cudaGetSymbolAddress((void**)&gEc, g_Ec);
  cudaGetSymbolAddress((void**)&gVv, g_Vv);
  cudaGetSymbolAddress((void**)&gWhi, g_Whi);
  cudaGetSymbolAddress((void**)&gWlo, g_Wlo);
  cudaGetSymbolAddress((void**)&gVhi, g_Vhi);
  cudaGetSymbolAddress((void**)&gVlo, g_Vlo);

  k_prep  <<<1, 256>>>(r_emb, Wr_W, Went_W);
  k_tables<<<1, 64>>>(eids, dist0);
  k_split <<<(kV*kH+255)/256, 256>>>(out_W, gWhi, gWlo, kV*kH);
  k_xgemm <<<dim3(8,64), 128>>>(tokens, emb, W_ih, b_ih, b_hh);
  k_lstm  <<<8, 256>>>(W_hh);
  k_gemvT <<<dim3(2,64), 128>>>(gH,  Wdelta_W, gGd, (const float*)0, (const float*)0);
  k_gemvT <<<dim3(2,64), 128>>>(gH,  Went_W,   gGe, (const float*)0, (const float*)0);
  k_entity<<<64, 32>>>(ents0, Wdelta_b);
  k_gemvT <<<dim3(2,64), 128>>>(gEc, We_W,     gVv, We_b, gH);
  k_split <<<(kT*kH+255)/256, 256>>>(gVv, gVhi, gVlo, kT*kH);
  k_heads <<<kT, 128>>>(out, Wr_b, Wlen_W, Wlen_b, Went_b, wdist_W, wdist_b, ents0);
  k_logits_mma<<<dim3((kV+127)/128, kT/128), 256>>>(out_b, out);
}